// round 2
// baseline (speedup 1.0000x reference)
#include <cuda_runtime.h>
#include <stdint.h>

// carry_save_adder: exact-binary reduction.
// S_b = sum over kept i of value(x[b,i,:]); out bits = S_b & 0xFFFF, carry = S_b >> 16.
// One warp per batch row. All 8 float4 loads batched up front (MLP=8),
// contribution built with FFMA-imm chains (bit-weight 2^((lane&3)*4) is
// loop-invariant and factored out), exact fp32 accumulation (< 2^22).

__global__ void __launch_bounds__(256)
csa_kernel(const float4* __restrict__ x, const int* __restrict__ mask,
           float* __restrict__ out, int B)
{
    const unsigned FULL = 0xFFFFFFFFu;
    const int lane = threadIdx.x & 31;
    const int warp = (blockIdx.x << 3) + (threadIdx.x >> 5);
    if (warp >= B) return;

    // Keep mask over the 64 values (indices 0,1 always kept).
    const unsigned mb_lo = __ballot_sync(FULL, mask[lane]      > 0) | 3u;
    const unsigned mb_hi = __ballot_sync(FULL, mask[lane + 32] > 0);

    const float4* row = x + (size_t)warp * 256;

    // ---- batch all loads first: 8 independent LDG.128 in flight ----
    float4 v[8];
    #pragma unroll
    for (int t = 0; t < 8; ++t)
        v[t] = row[lane + (t << 5)];

    // Value index for chunk t is i = 8t + (lane>>2); bit offset (lane&3)*4 is
    // the same for every t, so it factors out of the accumulation.
    const unsigned q = (unsigned)lane >> 2;
    float keepf[8];
    #pragma unroll
    for (int t = 0; t < 8; ++t) {
        unsigned bit = (t < 4) ? ((mb_lo >> (8 * t + q)) & 1u)
                               : ((mb_hi >> (8 * (t - 4) + q)) & 1u);
        keepf[t] = bit ? 1.0f : 0.0f;
    }

    float sumf = 0.0f;
    #pragma unroll
    for (int t = 0; t < 8; ++t) {
        float part = v[t].x;
        part = fmaf(v[t].y, 2.0f, part);
        part = fmaf(v[t].z, 4.0f, part);
        part = fmaf(v[t].w, 8.0f, part);
        sumf = fmaf(part, keepf[t], sumf);
    }
    // Apply the per-thread nibble weight 2^((lane&3)*4) once.
    sumf *= __int_as_float((127 + (((int)lane & 3) << 2)) << 23);

    // Warp reduction (exact: integer-valued floats, total < 2^22).
    #pragma unroll
    for (int off = 16; off; off >>= 1)
        sumf += __shfl_xor_sync(FULL, sumf, off);

    const unsigned s = (unsigned)sumf;

    // Write output bits (lanes 0..15) and carry (lane 16).
    if (lane < 16)
        out[(size_t)warp * 16 + lane] = (float)((s >> lane) & 1u);
    else if (lane == 16)
        out[(size_t)B * 16 + warp] = (float)(s >> 16);
}

extern "C" void kernel_launch(void* const* d_in, const int* in_sizes, int n_in,
                              void* d_out, int out_size)
{
    const float4* x   = (const float4*)d_in[0];   // (B, 64, 16) float32
    const int*    msk = (const int*)d_in[1];      // (64,) int32
    float*        out = (float*)d_out;            // B*16 output bits, then B carries

    int B = in_sizes[0] / 1024;                   // 64*16 floats per batch row
    int blocks = (B + 7) / 8;                     // 8 warps (rows) per block
    csa_kernel<<<blocks, 256>>>(x, msk, out, B);
}